// round 1
// baseline (speedup 1.0000x reference)
#include <cuda_runtime.h>
#include <math.h>

#define H 2048
#define S 2048
#define V 50257
#define RCHUNKS 16

// Scratch (device globals — no allocation allowed)
__device__ float g_emb[H];            // embeddings_index[input_id]
__device__ float g_part[RCHUNKS * H]; // partial column sums of encoder_outputs
__device__ float g_colsum[H];         // attn_applied
__device__ float g_x[H];              // relu(comb output)
__device__ float g_gx[3 * H];         // w_ih @ x + b_ih
__device__ float g_gh[3 * H];         // w_hh @ h0 + b_hh
__device__ float g_hnew[H];
__device__ float g_lse;

// ---------------------------------------------------------------------------
// K0: gather embedding row, write attn_weights (= 1.0) output region
__global__ void k_init(const int* __restrict__ input_id,
                       const float* __restrict__ emb,
                       float* __restrict__ out_attn) {
    int i = blockIdx.x * blockDim.x + threadIdx.x;
    if (i < H) g_emb[i] = emb[(size_t)(*input_id) * H + i];
    if (i < S) out_attn[i] = 1.0f;
}

// K1: partial column sums of encoder_outputs (S x H), deterministic two-stage
__global__ void k_colsum1(const float* __restrict__ enc) {
    int col = blockIdx.x * blockDim.x + threadIdx.x;    // 0..H-1
    int r0 = blockIdx.y * (S / RCHUNKS);
    float s = 0.f;
    #pragma unroll 8
    for (int r = 0; r < S / RCHUNKS; ++r)
        s += enc[(size_t)(r0 + r) * H + col];
    g_part[blockIdx.y * H + col] = s;
}

__global__ void k_colsum2() {
    int col = blockIdx.x * blockDim.x + threadIdx.x;
    float s = 0.f;
    #pragma unroll
    for (int c = 0; c < RCHUNKS; ++c) s += g_part[c * H + col];
    g_colsum[col] = s;
}

// ---------------------------------------------------------------------------
// Warp-per-row fp32 matvec helpers
__device__ __forceinline__ float warp_reduce(float v) {
    #pragma unroll
    for (int o = 16; o > 0; o >>= 1) v += __shfl_xor_sync(0xFFFFFFFFu, v, o);
    return v;
}

__device__ __forceinline__ float dot_row_1024(const float4* __restrict__ w,
                                              const float4* __restrict__ x,
                                              int lane) {
    // 512 float4 per row (H=2048 floats), 16 iters per lane, fully unrolled
    float acc = 0.f;
    #pragma unroll
    for (int j = lane; j < H / 4; j += 32) {
        float4 a = w[j];
        float4 b = x[j];
        acc = fmaf(a.x, b.x, acc);
        acc = fmaf(a.y, b.y, acc);
        acc = fmaf(a.z, b.z, acc);
        acc = fmaf(a.w, b.w, acc);
    }
    return acc;
}

// K2: comb matvec (H rows x 2H cols) over [emb | colsum], + bias, relu
__global__ void k_comb(const float* __restrict__ comb_w,
                       const float* __restrict__ comb_b) {
    int warp = (blockIdx.x * blockDim.x + threadIdx.x) >> 5;
    int lane = threadIdx.x & 31;
    if (warp >= H) return;
    const float4* wr = (const float4*)(comb_w + (size_t)warp * 2 * H);
    float acc = dot_row_1024(wr,          (const float4*)g_emb,    lane);
    acc      += dot_row_1024(wr + H / 4,  (const float4*)g_colsum, lane);
    acc = warp_reduce(acc);
    if (lane == 0) g_x[warp] = fmaxf(acc + comb_b[warp], 0.f);
}

// K3: GRU gate matvecs. 6H warp-rows: first 3H -> gx (w_ih @ x), next 3H -> gh (w_hh @ h0)
__global__ void k_gates(const float* __restrict__ w_ih,
                        const float* __restrict__ w_hh,
                        const float* __restrict__ b_ih,
                        const float* __restrict__ b_hh,
                        const float* __restrict__ h0) {
    int warp = (blockIdx.x * blockDim.x + threadIdx.x) >> 5;
    int lane = threadIdx.x & 31;
    if (warp >= 6 * H) return;
    bool is_hh = warp >= 3 * H;
    int row = is_hh ? warp - 3 * H : warp;
    const float* wmat = is_hh ? w_hh : w_ih;
    const float4* wr = (const float4*)(wmat + (size_t)row * H);
    const float4* xv = is_hh ? (const float4*)h0 : (const float4*)g_x;
    float acc = dot_row_1024(wr, xv, lane);
    acc = warp_reduce(acc);
    if (lane == 0) {
        if (is_hh) g_gh[row] = acc + b_hh[row];
        else       g_gx[row] = acc + b_ih[row];
    }
}

// K4: GRU gate combine -> h_new; also writes h_new output region
__global__ void k_gru(const float* __restrict__ h0, float* __restrict__ out_h) {
    int i = blockIdx.x * blockDim.x + threadIdx.x;
    if (i >= H) return;
    float r = 1.f / (1.f + expf(-(g_gx[i]         + g_gh[i])));
    float z = 1.f / (1.f + expf(-(g_gx[H + i]     + g_gh[H + i])));
    float n = tanhf(g_gx[2 * H + i] + r * g_gh[2 * H + i]);
    float hn = (1.f - z) * n + z * h0[i];
    g_hnew[i] = hn;
    out_h[i]  = hn;
}

// K5: out matvec (V rows x H cols) -> raw logits into d_out[0..V)
__global__ void k_out(const float* __restrict__ out_w,
                      const float* __restrict__ out_b,
                      float* __restrict__ out) {
    int warp = (blockIdx.x * blockDim.x + threadIdx.x) >> 5;
    int lane = threadIdx.x & 31;
    if (warp >= V) return;
    const float4* wr = (const float4*)(out_w + (size_t)warp * H);
    float acc = dot_row_1024(wr, (const float4*)g_hnew, lane);
    acc = warp_reduce(acc);
    if (lane == 0) out[warp] = acc + out_b[warp];
}

// K6: single-block logsumexp over logits (V ~ 50K, L2-resident -> fast)
__global__ void k_lse(const float* __restrict__ logits) {
    __shared__ float sm[1024];
    int t = threadIdx.x;
    float m = -INFINITY;
    for (int i = t; i < V; i += 1024) m = fmaxf(m, logits[i]);
    sm[t] = m; __syncthreads();
    #pragma unroll
    for (int s = 512; s > 0; s >>= 1) {
        if (t < s) sm[t] = fmaxf(sm[t], sm[t + s]);
        __syncthreads();
    }
    float mx = sm[0]; __syncthreads();
    float sum = 0.f;
    for (int i = t; i < V; i += 1024) sum += expf(logits[i] - mx);
    sm[t] = sum; __syncthreads();
    #pragma unroll
    for (int s = 512; s > 0; s >>= 1) {
        if (t < s) sm[t] += sm[t + s];
        __syncthreads();
    }
    if (t == 0) g_lse = mx + logf(sm[0]);
}

// K7: log_probs = logits - lse (in place)
__global__ void k_sub(float* __restrict__ out) {
    int i = blockIdx.x * blockDim.x + threadIdx.x;
    if (i < V) out[i] -= g_lse;
}

// ---------------------------------------------------------------------------
extern "C" void kernel_launch(void* const* d_in, const int* in_sizes, int n_in,
                              void* d_out, int out_size) {
    const int*   input_id = (const int*)  d_in[0];
    const float* hidden   = (const float*)d_in[1];   // (1,1,H) -> h0
    const float* enc      = (const float*)d_in[2];   // (S,H)
    const float* emb      = (const float*)d_in[3];   // (V,H)
    // d_in[4] attn_w, d_in[5] attn_b: dead (softmax over singleton)
    const float* comb_w   = (const float*)d_in[6];   // (H,2H)
    const float* comb_b   = (const float*)d_in[7];   // (H,)
    const float* w_ih     = (const float*)d_in[8];   // (3H,H)
    const float* w_hh     = (const float*)d_in[9];   // (3H,H)
    const float* b_ih     = (const float*)d_in[10];  // (3H,)
    const float* b_hh     = (const float*)d_in[11];  // (3H,)
    const float* out_w    = (const float*)d_in[12];  // (V,H)
    const float* out_b    = (const float*)d_in[13];  // (V,)
    float* out = (float*)d_out; // layout: [log_probs(V) | h_new(H) | attn_weights(S)]

    k_init<<<(S + 255) / 256, 256>>>(input_id, emb, out + V + H);
    k_colsum1<<<dim3(H / 256, RCHUNKS), 256>>>(enc);
    k_colsum2<<<H / 256, 256>>>();
    k_comb<<<(H * 32) / 256, 256>>>(comb_w, comb_b);
    k_gates<<<(6 * H * 32) / 256, 256>>>(w_ih, w_hh, b_ih, b_hh, hidden);
    k_gru<<<(H + 255) / 256, 256>>>(hidden, out + V);
    k_out<<<(V * 32 + 255) / 256, 256>>>(out_w, out_b, out);
    k_lse<<<1, 1024>>>(out);
    k_sub<<<(V + 255) / 256, 256>>>(out);
}

// round 2
// speedup vs baseline: 1.1652x; 1.1652x over previous
#include <cuda_runtime.h>
#include <math.h>

#define H 2048
#define S 2048
#define V 50257
#define RCH 16
#define NLSE 128

// Scratch (device globals — no allocation allowed)
__device__ float g_emb[H];
__device__ float g_part[RCH * H];
__device__ float g_colsum[H];
__device__ float g_x[H];
__device__ float g_gx[3 * H];
__device__ float g_gh[3 * H];
__device__ float g_hnew[H];
__device__ float g_pmax[NLSE];
__device__ float g_psum[NLSE];

__device__ __forceinline__ float warp_reduce(float v) {
    #pragma unroll
    for (int o = 16; o > 0; o >>= 1) v += __shfl_xor_sync(0xFFFFFFFFu, v, o);
    return v;
}

// Dot over 512 float4 (2048 floats) per warp: 16 float4/lane.
// Loads are explicitly batched into registers BEFORE FMAs so ptxas keeps
// 16 LDG.128 in flight per lane (MLP_eff ~16 instead of ~4 at 44 regs).
__device__ __forceinline__ float dot512(const float4* __restrict__ w,
                                        const float4* __restrict__ x, int lane) {
    float4 wa[8], wb[8];
    #pragma unroll
    for (int b = 0; b < 8; b++) wa[b] = w[lane + 32 * b];
    #pragma unroll
    for (int b = 0; b < 8; b++) wb[b] = w[lane + 32 * (8 + b)];
    float acc = 0.f;
    #pragma unroll
    for (int b = 0; b < 8; b++) {
        float4 xv = x[lane + 32 * b];
        acc = fmaf(wa[b].x, xv.x, acc); acc = fmaf(wa[b].y, xv.y, acc);
        acc = fmaf(wa[b].z, xv.z, acc); acc = fmaf(wa[b].w, xv.w, acc);
    }
    #pragma unroll
    for (int b = 0; b < 8; b++) {
        float4 xv = x[lane + 32 * (8 + b)];
        acc = fmaf(wb[b].x, xv.x, acc); acc = fmaf(wb[b].y, xv.y, acc);
        acc = fmaf(wb[b].z, xv.z, acc); acc = fmaf(wb[b].w, xv.w, acc);
    }
    return acc;
}

// ---------------------------------------------------------------------------
// K_A (fused, independent work): gh = w_hh@h0 + b_hh  |  colsum partials of
// encoder_outputs  |  emb gather + attn ones.
#define GH_BLOCKS 768     // 6144 warp-rows
#define CS_BLOCKS 128     // 16 chunks x 8 col-blocks
#define MISC_BLOCKS 8     // 2048 elems
__global__ __launch_bounds__(256) void k_A(const float* __restrict__ w_hh,
                                           const float* __restrict__ b_hh,
                                           const float* __restrict__ h0,
                                           const float* __restrict__ enc,
                                           const int* __restrict__ input_id,
                                           const float* __restrict__ emb,
                                           float* __restrict__ out_attn) {
    int b = blockIdx.x;
    if (b < GH_BLOCKS) {
        int warp = (b * 256 + threadIdx.x) >> 5;   // 0..6143
        int lane = threadIdx.x & 31;
        float acc = dot512((const float4*)(w_hh + (size_t)warp * H),
                           (const float4*)h0, lane);
        acc = warp_reduce(acc);
        if (lane == 0) g_gh[warp] = acc + b_hh[warp];
    } else if (b < GH_BLOCKS + CS_BLOCKS) {
        int idx = b - GH_BLOCKS;
        int chunk = idx >> 3;           // 0..15
        int colb = idx & 7;             // 0..7
        int col = colb * 256 + threadIdx.x;
        int r0 = chunk * (S / RCH);
        float s = 0.f;
        #pragma unroll 8
        for (int r = 0; r < S / RCH; ++r)
            s += enc[(size_t)(r0 + r) * H + col];
        g_part[chunk * H + col] = s;
    } else {
        int i = (b - GH_BLOCKS - CS_BLOCKS) * 256 + threadIdx.x;  // 0..2047
        g_emb[i] = emb[(size_t)(*input_id) * H + i];
        out_attn[i] = 1.0f;
    }
}

// K_B: finish column sums
__global__ void k_colsum2() {
    int col = blockIdx.x * 256 + threadIdx.x;
    float s = 0.f;
    #pragma unroll
    for (int c = 0; c < RCH; ++c) s += g_part[c * H + col];
    g_colsum[col] = s;
}

// K_C: comb matvec (H rows x 2H cols), 2 warps per row (K-split), relu
__global__ __launch_bounds__(256) void k_comb(const float* __restrict__ comb_w,
                                              const float* __restrict__ comb_b) {
    __shared__ float sp[8];
    int w = threadIdx.x >> 5, lane = threadIdx.x & 31;
    int row = blockIdx.x * 4 + (w >> 1);
    int half = w & 1;
    const float4* wr = (const float4*)(comb_w + (size_t)row * 2 * H + half * H);
    const float4* xv = half ? (const float4*)g_colsum : (const float4*)g_emb;
    float acc = dot512(wr, xv, lane);
    acc = warp_reduce(acc);
    if (lane == 0) sp[w] = acc;
    __syncthreads();
    if (lane == 0 && half == 0) {
        float r = sp[w] + sp[w + 1] + comb_b[row];
        g_x[row] = fmaxf(r, 0.f);
    }
}

// K_D: gx = w_ih @ relu_x + b_ih   (3H warp-rows)
__global__ __launch_bounds__(256) void k_gates_ih(const float* __restrict__ w_ih,
                                                  const float* __restrict__ b_ih) {
    int warp = (blockIdx.x * 256 + threadIdx.x) >> 5;  // 0..6143
    int lane = threadIdx.x & 31;
    float acc = dot512((const float4*)(w_ih + (size_t)warp * H),
                       (const float4*)g_x, lane);
    acc = warp_reduce(acc);
    if (lane == 0) g_gx[warp] = acc + b_ih[warp];
}

// K_E: GRU gate combine -> h_new (also to output)
__global__ void k_gru(const float* __restrict__ h0, float* __restrict__ out_h) {
    int i = blockIdx.x * 256 + threadIdx.x;
    float r = 1.f / (1.f + expf(-(g_gx[i]         + g_gh[i])));
    float z = 1.f / (1.f + expf(-(g_gx[H + i]     + g_gh[H + i])));
    float n = tanhf(g_gx[2 * H + i] + r * g_gh[2 * H + i]);
    float hn = (1.f - z) * n + z * h0[i];
    g_hnew[i] = hn;
    out_h[i]  = hn;
}

// K_F: out matvec (V rows x H cols) -> raw logits
__global__ __launch_bounds__(256) void k_out(const float* __restrict__ out_w,
                                             const float* __restrict__ out_b,
                                             float* __restrict__ out) {
    int warp = (blockIdx.x * 256 + threadIdx.x) >> 5;
    int lane = threadIdx.x & 31;
    if (warp >= V) return;
    float acc = dot512((const float4*)(out_w + (size_t)warp * H),
                       (const float4*)g_hnew, lane);
    acc = warp_reduce(acc);
    if (lane == 0) out[warp] = acc + out_b[warp];
}

// K_G: per-block (max, sumexp) partials over logits
__global__ void k_lse1(const float* __restrict__ logits) {
    __shared__ float sm[256];
    int t = threadIdx.x;
    float m = -INFINITY;
    for (int i = blockIdx.x * 256 + t; i < V; i += NLSE * 256) m = fmaxf(m, logits[i]);
    sm[t] = m; __syncthreads();
    #pragma unroll
    for (int s = 128; s > 0; s >>= 1) {
        if (t < s) sm[t] = fmaxf(sm[t], sm[t + s]);
        __syncthreads();
    }
    float mx = sm[0]; __syncthreads();
    float sum = 0.f;
    for (int i = blockIdx.x * 256 + t; i < V; i += NLSE * 256) sum += expf(logits[i] - mx);
    sm[t] = sum; __syncthreads();
    #pragma unroll
    for (int s = 128; s > 0; s >>= 1) {
        if (t < s) sm[t] += sm[t + s];
        __syncthreads();
    }
    if (t == 0) { g_pmax[blockIdx.x] = mx; g_psum[blockIdx.x] = sm[0]; }
}

// K_H: each block redundantly (deterministically) combines partials, subtracts
__global__ void k_sub(float* __restrict__ out) {
    __shared__ float lse;
    int t = threadIdx.x;
    if (t == 0) {
        float M = -INFINITY;
        for (int i = 0; i < NLSE; i++) M = fmaxf(M, g_pmax[i]);
        float sum = 0.f;
        for (int i = 0; i < NLSE; i++) sum += g_psum[i] * expf(g_pmax[i] - M);
        lse = M + logf(sum);
    }
    __syncthreads();
    int i = blockIdx.x * 256 + t;
    if (i < V) out[i] -= lse;
}

// ---------------------------------------------------------------------------
extern "C" void kernel_launch(void* const* d_in, const int* in_sizes, int n_in,
                              void* d_out, int out_size) {
    const int*   input_id = (const int*)  d_in[0];
    const float* hidden   = (const float*)d_in[1];   // (1,1,H) -> h0
    const float* enc      = (const float*)d_in[2];   // (S,H)
    const float* emb      = (const float*)d_in[3];   // (V,H)
    // d_in[4] attn_w, d_in[5] attn_b: dead (softmax over singleton)
    const float* comb_w   = (const float*)d_in[6];   // (H,2H)
    const float* comb_b   = (const float*)d_in[7];   // (H,)
    const float* w_ih     = (const float*)d_in[8];   // (3H,H)
    const float* w_hh     = (const float*)d_in[9];   // (3H,H)
    const float* b_ih     = (const float*)d_in[10];  // (3H,)
    const float* b_hh     = (const float*)d_in[11];  // (3H,)
    const float* out_w    = (const float*)d_in[12];  // (V,H)
    const float* out_b    = (const float*)d_in[13];  // (V,)
    float* out = (float*)d_out; // [log_probs(V) | h_new(H) | attn_weights(S)]

    k_A<<<GH_BLOCKS + CS_BLOCKS + MISC_BLOCKS, 256>>>(w_hh, b_hh, hidden, enc,
                                                      input_id, emb, out + V + H);
    k_colsum2<<<H / 256, 256>>>();
    k_comb<<<H / 4, 256>>>(comb_w, comb_b);
    k_gates_ih<<<(3 * H * 32) / 256, 256>>>(w_ih, b_ih);
    k_gru<<<H / 256, 256>>>(hidden, out + V);
    k_out<<<(V * 32 + 255) / 256, 256>>>(out_w, out_b, out);
    k_lse1<<<NLSE, 256>>>(out);
    k_sub<<<(V + 255) / 256, 256>>>(out);
}

// round 5
// speedup vs baseline: 1.1854x; 1.0173x over previous
#include <cuda_runtime.h>
#include <math.h>

#define H 2048
#define S 2048
#define V 50257
#define RCH 16
#define NB_LSE 64

// Scratch (device globals — no allocation allowed)
__device__ float g_emb[H];
__device__ float g_part[RCH * H];
__device__ float g_colsum[H];
__device__ float g_x[H];
__device__ float g_gx[3 * H];
__device__ float g_gh[3 * H];
__device__ float g_hnew[H];
__device__ float g_pmax[NB_LSE];
__device__ float g_psum[NB_LSE];
__device__ int g_count;                 // zero-initialized
__device__ volatile int g_release;      // monotonic epoch

__device__ __forceinline__ float warp_reduce(float v) {
    #pragma unroll
    for (int o = 16; o > 0; o >>= 1) v += __shfl_xor_sync(0xFFFFFFFFu, v, o);
    return v;
}

// Warp dot over 512 float4 (H floats): w streamed from global (8-batched
// LDG.128 so many loads stay in flight), x read from SHARED (LDS port —
// does not compete with the LDG/L1tex path).
__device__ __forceinline__ float dot512s(const float4* __restrict__ w,
                                         const float4* __restrict__ sx,
                                         int lane) {
    float acc = 0.f;
    #pragma unroll
    for (int h = 0; h < 2; h++) {
        float4 wa[8];
        #pragma unroll
        for (int b = 0; b < 8; b++) wa[b] = w[lane + 32 * (8 * h + b)];
        #pragma unroll
        for (int b = 0; b < 8; b++) {
            float4 xv = sx[lane + 32 * (8 * h + b)];
            acc = fmaf(wa[b].x, xv.x, acc); acc = fmaf(wa[b].y, xv.y, acc);
            acc = fmaf(wa[b].z, xv.z, acc); acc = fmaf(wa[b].w, xv.w, acc);
        }
    }
    return acc;
}

// ---------------------------------------------------------------------------
// K_A (fused independent work): gh = w_hh@h0 + b_hh | colsum partials | misc
#define GH_BLOCKS 768
#define CS_BLOCKS 128
#define MISC_BLOCKS 8
__global__ __launch_bounds__(256) void k_A(const float* __restrict__ w_hh,
                                           const float* __restrict__ b_hh,
                                           const float* __restrict__ h0,
                                           const float* __restrict__ enc,
                                           const int* __restrict__ input_id,
                                           const float* __restrict__ emb,
                                           float* __restrict__ out_attn) {
    __shared__ float4 sx[H / 4];
    int b = blockIdx.x;
    if (b < GH_BLOCKS) {
        // stage h0 into smem
        const float4* x4 = (const float4*)h0;
        sx[threadIdx.x] = x4[threadIdx.x];
        sx[threadIdx.x + 256] = x4[threadIdx.x + 256];
        __syncthreads();
        int w = threadIdx.x >> 5, lane = threadIdx.x & 31;
        int row = b * 8 + w;                     // 0..6143
        float acc = dot512s((const float4*)(w_hh + (size_t)row * H), sx, lane);
        acc = warp_reduce(acc);
        if (lane == 0) g_gh[row] = acc + b_hh[row];
    } else if (b < GH_BLOCKS + CS_BLOCKS) {
        int idx = b - GH_BLOCKS;
        int chunk = idx >> 3;                    // 0..15
        int colb = idx & 7;                      // 0..7
        int col = colb * 256 + threadIdx.x;
        int r0 = chunk * (S / RCH);
        float s = 0.f;
        #pragma unroll 8
        for (int r = 0; r < S / RCH; ++r)
            s += enc[(size_t)(r0 + r) * H + col];
        g_part[chunk * H + col] = s;
    } else {
        int i = (b - GH_BLOCKS - CS_BLOCKS) * 256 + threadIdx.x;  // 0..2047
        g_emb[i] = emb[(size_t)(*input_id) * H + i];
        out_attn[i] = 1.0f;
    }
}

// K_B: finish column sums
__global__ void k_colsum2() {
    int col = blockIdx.x * 256 + threadIdx.x;
    float s = 0.f;
    #pragma unroll
    for (int c = 0; c < RCH; ++c) s += g_part[c * H + col];
    g_colsum[col] = s;
}

// K_C: comb matvec (H rows x 2H cols), warp-per-row, x = [emb | colsum] in smem
__global__ __launch_bounds__(256) void k_comb(const float* __restrict__ comb_w,
                                              const float* __restrict__ comb_b) {
    __shared__ float4 se[H / 4];
    __shared__ float4 sc[H / 4];
    const float4* e4 = (const float4*)g_emb;
    const float4* c4 = (const float4*)g_colsum;
    se[threadIdx.x] = e4[threadIdx.x];
    se[threadIdx.x + 256] = e4[threadIdx.x + 256];
    sc[threadIdx.x] = c4[threadIdx.x];
    sc[threadIdx.x + 256] = c4[threadIdx.x + 256];
    __syncthreads();
    int w = threadIdx.x >> 5, lane = threadIdx.x & 31;
    int row = blockIdx.x * 8 + w;                // 0..2047
    const float4* wr = (const float4*)(comb_w + (size_t)row * 2 * H);
    float acc = dot512s(wr, se, lane) + dot512s(wr + H / 4, sc, lane);
    acc = warp_reduce(acc);
    if (lane == 0) g_x[row] = fmaxf(acc + comb_b[row], 0.f);
}

// K_D: gx = w_ih @ relu_x + b_ih   (3H rows), x in smem
__global__ __launch_bounds__(256) void k_gates_ih(const float* __restrict__ w_ih,
                                                  const float* __restrict__ b_ih) {
    __shared__ float4 sx[H / 4];
    const float4* x4 = (const float4*)g_x;
    sx[threadIdx.x] = x4[threadIdx.x];
    sx[threadIdx.x + 256] = x4[threadIdx.x + 256];
    __syncthreads();
    int w = threadIdx.x >> 5, lane = threadIdx.x & 31;
    int row = blockIdx.x * 8 + w;                // 0..6143
    float acc = dot512s((const float4*)(w_ih + (size_t)row * H), sx, lane);
    acc = warp_reduce(acc);
    if (lane == 0) g_gx[row] = acc + b_ih[row];
}

// K_E: GRU gate combine -> h_new
__global__ void k_gru(const float* __restrict__ h0, float* __restrict__ out_h) {
    int i = blockIdx.x * 256 + threadIdx.x;
    float r = 1.f / (1.f + expf(-(g_gx[i]         + g_gh[i])));
    float z = 1.f / (1.f + expf(-(g_gx[H + i]     + g_gh[H + i])));
    float n = tanhf(g_gx[2 * H + i] + r * g_gh[2 * H + i]);
    float hn = (1.f - z) * n + z * h0[i];
    g_hnew[i] = hn;
    out_h[i]  = hn;
}

// K_F: out matvec (V rows x H cols) -> raw logits, h_new in smem
__global__ __launch_bounds__(256) void k_out(const float* __restrict__ out_w,
                                             const float* __restrict__ out_b,
                                             float* __restrict__ out) {
    __shared__ float4 sx[H / 4];
    const float4* x4 = (const float4*)g_hnew;
    sx[threadIdx.x] = x4[threadIdx.x];
    sx[threadIdx.x + 256] = x4[threadIdx.x + 256];
    __syncthreads();
    int w = threadIdx.x >> 5, lane = threadIdx.x & 31;
    int row = blockIdx.x * 8 + w;
    if (row >= V) return;
    float acc = dot512s((const float4*)(out_w + (size_t)row * H), sx, lane);
    acc = warp_reduce(acc);
    if (lane == 0) out[row] = acc + out_b[row];
}

// K_G: fused log-softmax normalize. 64 blocks, logits held in registers
// across a global spin barrier (64 blocks are always co-resident).
__global__ __launch_bounds__(256) void k_lsesub(float* __restrict__ out) {
    __shared__ float sm[256];
    __shared__ float s_lse;
    int t = threadIdx.x;
    int gtid = blockIdx.x * 256 + t;
    float v[4];
    float m = -INFINITY;
    #pragma unroll
    for (int k = 0; k < 4; k++) {
        int i = gtid + k * (NB_LSE * 256);
        v[k] = (i < V) ? out[i] : -INFINITY;
        m = fmaxf(m, v[k]);
    }
    sm[t] = m; __syncthreads();
    #pragma unroll
    for (int s = 128; s > 0; s >>= 1) {
        if (t < s) sm[t] = fmaxf(sm[t], sm[t + s]);
        __syncthreads();
    }
    float bmax = sm[0]; __syncthreads();
    float sum = 0.f;
    #pragma unroll
    for (int k = 0; k < 4; k++)
        sum += (v[k] > -INFINITY) ? expf(v[k] - bmax) : 0.f;
    sm[t] = sum; __syncthreads();
    #pragma unroll
    for (int s = 128; s > 0; s >>= 1) {
        if (t < s) sm[t] += sm[t + s];
        __syncthreads();
    }
    if (t == 0) { g_pmax[blockIdx.x] = bmax; g_psum[blockIdx.x] = sm[0]; }
    // global barrier (epoch-based, replay-safe)
    __threadfence();
    __syncthreads();
    if (t == 0) {
        int my = g_release;
        int c = atomicAdd(&g_count, 1);
        if (c == NB_LSE - 1) {
            g_count = 0;
            __threadfence();
            atomicAdd((int*)&g_release, 1);
        } else {
            while (g_release == my) { __nanosleep(64); }
        }
        __threadfence();
        // combine partials (redundant per block, deterministic)
        float M = -INFINITY;
        for (int i = 0; i < NB_LSE; i++) M = fmaxf(M, g_pmax[i]);
        float ssum = 0.f;
        for (int i = 0; i < NB_LSE; i++) ssum += g_psum[i] * expf(g_pmax[i] - M);
        s_lse = M + logf(ssum);
    }
    __syncthreads();
    float lse = s_lse;
    #pragma unroll
    for (int k = 0; k < 4; k++) {
        int i = gtid + k * (NB_LSE * 256);
        if (i < V) out[i] = v[k] - lse;
    }
}

// ---------------------------------------------------------------------------
extern "C" void kernel_launch(void* const* d_in, const int* in_sizes, int n_in,
                              void* d_out, int out_size) {
    const int*   input_id = (const int*)  d_in[0];
    const float* hidden   = (const float*)d_in[1];
    const float* enc      = (const float*)d_in[2];
    const float* emb      = (const float*)d_in[3];
    // d_in[4], d_in[5]: attn linear — dead (softmax over singleton)
    const float* comb_w   = (const float*)d_in[6];
    const float* comb_b   = (const float*)d_in[7];
    const float* w_ih     = (const float*)d_in[8];
    const float* w_hh     = (const float*)d_in[9];
    const float* b_ih     = (const float*)d_in[10];
    const float* b_hh     = (const float*)d_in[11];
    const float* out_w    = (const float*)d_in[12];
    const float* out_b    = (const float*)d_in[13];
    float* out = (float*)d_out; // [log_probs(V) | h_new(H) | attn_weights(S)]

    k_A<<<GH_BLOCKS + CS_BLOCKS + MISC_BLOCKS, 256>>>(w_hh, b_hh, hidden, enc,
                                                      input_id, emb, out + V + H);
    k_colsum2<<<H / 256, 256>>>();
    k_comb<<<H / 8, 256>>>(comb_w, comb_b);
    k_gates_ih<<<(3 * H) / 8, 256>>>(w_ih, b_ih);
    k_gru<<<H / 256, 256>>>(hidden, out + V);
    k_out<<<(V + 7) / 8, 256>>>(out_w, out_b, out);
    k_lsesub<<<NB_LSE, 256>>>(out);
}

// round 6
// speedup vs baseline: 1.1937x; 1.0071x over previous
#include <cuda_runtime.h>
#include <math.h>

#define H 2048
#define S 2048
#define V 50257
#define RCH 16
#define NB_LSE 64

// Scratch (device globals — no allocation allowed)
__device__ float g_emb[H];
__device__ float g_part[RCH * H];
__device__ float g_colsum[H];
__device__ float g_x[H];
__device__ float g_gx[3 * H];
__device__ float g_gh[3 * H];
__device__ float g_hnew[H];
__device__ float g_pmax[NB_LSE];
__device__ float g_psum[NB_LSE];
__device__ int g_count;                 // zero-initialized
__device__ volatile int g_release;      // monotonic epoch

__device__ __forceinline__ float warp_reduce(float v) {
    #pragma unroll
    for (int o = 16; o > 0; o >>= 1) v += __shfl_xor_sync(0xFFFFFFFFu, v, o);
    return v;
}

// Two-row warp dot over H floats (512 float4). Independent accumulators give
// two dependence chains; per phase 8 independent LDG.128 stay in flight and
// next-phase loads overlap current-phase FMAs. __ldcs: streaming weights.
__device__ __forceinline__ void dot2(const float4* __restrict__ w0,
                                     const float4* __restrict__ w1,
                                     const float4* __restrict__ sx,
                                     int lane, float& acc0, float& acc1) {
    #pragma unroll
    for (int p = 0; p < 4; p++) {
        float4 a0[4], a1[4];
        #pragma unroll
        for (int b = 0; b < 4; b++) a0[b] = __ldcs(&w0[lane + 32 * (4 * p + b)]);
        #pragma unroll
        for (int b = 0; b < 4; b++) a1[b] = __ldcs(&w1[lane + 32 * (4 * p + b)]);
        #pragma unroll
        for (int b = 0; b < 4; b++) {
            float4 xv = sx[lane + 32 * (4 * p + b)];
            acc0 = fmaf(a0[b].x, xv.x, acc0); acc0 = fmaf(a0[b].y, xv.y, acc0);
            acc0 = fmaf(a0[b].z, xv.z, acc0); acc0 = fmaf(a0[b].w, xv.w, acc0);
            acc1 = fmaf(a1[b].x, xv.x, acc1); acc1 = fmaf(a1[b].y, xv.y, acc1);
            acc1 = fmaf(a1[b].z, xv.z, acc1); acc1 = fmaf(a1[b].w, xv.w, acc1);
        }
    }
}

// ---------------------------------------------------------------------------
// K_A (fused independent work): gh = w_hh@h0 + b_hh | colsum partials | misc
#define GH_BLOCKS 384      // 6144 rows, 16 rows/block (2 per warp)
#define CS_BLOCKS 128      // 16 chunks x 8 col-blocks
#define MISC_BLOCKS 8      // 2048 elems
__global__ __launch_bounds__(256, 3) void k_A(const float* __restrict__ w_hh,
                                              const float* __restrict__ b_hh,
                                              const float* __restrict__ h0,
                                              const float* __restrict__ enc,
                                              const int* __restrict__ input_id,
                                              const float* __restrict__ emb,
                                              float* __restrict__ out_attn) {
    __shared__ float4 sx[H / 4];
    int b = blockIdx.x;
    if (b < GH_BLOCKS) {
        const float4* x4 = (const float4*)h0;
        sx[threadIdx.x] = x4[threadIdx.x];
        sx[threadIdx.x + 256] = x4[threadIdx.x + 256];
        __syncthreads();
        int w = threadIdx.x >> 5, lane = threadIdx.x & 31;
        int r0 = b * 16 + w * 2;                 // 0..6142
        const float4* w0 = (const float4*)(w_hh + (size_t)r0 * H);
        float acc0 = 0.f, acc1 = 0.f;
        dot2(w0, w0 + H / 4, sx, lane, acc0, acc1);
        acc0 = warp_reduce(acc0);
        acc1 = warp_reduce(acc1);
        if (lane == 0) {
            g_gh[r0]     = acc0 + b_hh[r0];
            g_gh[r0 + 1] = acc1 + b_hh[r0 + 1];
        }
    } else if (b < GH_BLOCKS + CS_BLOCKS) {
        int idx = b - GH_BLOCKS;
        int chunk = idx >> 3;                    // 0..15
        int colb = idx & 7;                      // 0..7
        int col = colb * 256 + threadIdx.x;
        int r0 = chunk * (S / RCH);
        float s = 0.f;
        #pragma unroll 8
        for (int r = 0; r < S / RCH; ++r)
            s += __ldcs(&enc[(size_t)(r0 + r) * H + col]);
        g_part[chunk * H + col] = s;
    } else {
        int i = (b - GH_BLOCKS - CS_BLOCKS) * 256 + threadIdx.x;  // 0..2047
        g_emb[i] = emb[(size_t)(*input_id) * H + i];
        out_attn[i] = 1.0f;
    }
}

// K_B: finish column sums
__global__ void k_colsum2() {
    int col = blockIdx.x * 256 + threadIdx.x;
    float s = 0.f;
    #pragma unroll
    for (int c = 0; c < RCH; ++c) s += g_part[c * H + col];
    g_colsum[col] = s;
}

// K_C: comb matvec (H rows x 2H cols), 2 rows/warp, x = [emb | colsum] in smem
__global__ __launch_bounds__(256, 3) void k_comb(const float* __restrict__ comb_w,
                                                 const float* __restrict__ comb_b) {
    __shared__ float4 se[H / 4];
    __shared__ float4 sc[H / 4];
    const float4* e4 = (const float4*)g_emb;
    const float4* c4 = (const float4*)g_colsum;
    se[threadIdx.x] = e4[threadIdx.x];
    se[threadIdx.x + 256] = e4[threadIdx.x + 256];
    sc[threadIdx.x] = c4[threadIdx.x];
    sc[threadIdx.x + 256] = c4[threadIdx.x + 256];
    __syncthreads();
    int w = threadIdx.x >> 5, lane = threadIdx.x & 31;
    int r0 = blockIdx.x * 16 + w * 2;            // 0..2046
    const float4* w0 = (const float4*)(comb_w + (size_t)r0 * 2 * H);
    const float4* w1 = w0 + 2 * H / 4;
    float acc0 = 0.f, acc1 = 0.f;
    dot2(w0, w1, se, lane, acc0, acc1);                    // emb half
    dot2(w0 + H / 4, w1 + H / 4, sc, lane, acc0, acc1);    // colsum half
    acc0 = warp_reduce(acc0);
    acc1 = warp_reduce(acc1);
    if (lane == 0) {
        g_x[r0]     = fmaxf(acc0 + comb_b[r0], 0.f);
        g_x[r0 + 1] = fmaxf(acc1 + comb_b[r0 + 1], 0.f);
    }
}

// K_D: gx = w_ih @ relu_x + b_ih   (3H rows), 2 rows/warp, x in smem
__global__ __launch_bounds__(256, 3) void k_gates_ih(const float* __restrict__ w_ih,
                                                     const float* __restrict__ b_ih) {
    __shared__ float4 sx[H / 4];
    const float4* x4 = (const float4*)g_x;
    sx[threadIdx.x] = x4[threadIdx.x];
    sx[threadIdx.x + 256] = x4[threadIdx.x + 256];
    __syncthreads();
    int w = threadIdx.x >> 5, lane = threadIdx.x & 31;
    int r0 = blockIdx.x * 16 + w * 2;            // 0..6142
    const float4* w0 = (const float4*)(w_ih + (size_t)r0 * H);
    float acc0 = 0.f, acc1 = 0.f;
    dot2(w0, w0 + H / 4, sx, lane, acc0, acc1);
    acc0 = warp_reduce(acc0);
    acc1 = warp_reduce(acc1);
    if (lane == 0) {
        g_gx[r0]     = acc0 + b_ih[r0];
        g_gx[r0 + 1] = acc1 + b_ih[r0 + 1];
    }
}

// K_E: GRU gate combine -> h_new
__global__ void k_gru(const float* __restrict__ h0, float* __restrict__ out_h) {
    int i = blockIdx.x * 256 + threadIdx.x;
    float r = 1.f / (1.f + expf(-(g_gx[i]         + g_gh[i])));
    float z = 1.f / (1.f + expf(-(g_gx[H + i]     + g_gh[H + i])));
    float n = tanhf(g_gx[2 * H + i] + r * g_gh[2 * H + i]);
    float hn = (1.f - z) * n + z * h0[i];
    g_hnew[i] = hn;
    out_h[i]  = hn;
}

// K_F: out matvec (V rows x H cols) -> raw logits, 2 rows/warp, h_new in smem
__global__ __launch_bounds__(256, 3) void k_out(const float* __restrict__ out_w,
                                                const float* __restrict__ out_b,
                                                float* __restrict__ out) {
    __shared__ float4 sx[H / 4];
    const float4* x4 = (const float4*)g_hnew;
    sx[threadIdx.x] = x4[threadIdx.x];
    sx[threadIdx.x + 256] = x4[threadIdx.x + 256];
    __syncthreads();
    int w = threadIdx.x >> 5, lane = threadIdx.x & 31;
    int r0 = blockIdx.x * 16 + w * 2;
    if (r0 >= V) return;
    const float4* w0 = (const float4*)(out_w + (size_t)r0 * H);
    float acc0 = 0.f, acc1 = 0.f;
    if (r0 + 1 < V) {
        dot2(w0, w0 + H / 4, sx, lane, acc0, acc1);
    } else {
        dot2(w0, w0, sx, lane, acc0, acc1);  // duplicate row; acc1 discarded
    }
    acc0 = warp_reduce(acc0);
    acc1 = warp_reduce(acc1);
    if (lane == 0) {
        out[r0] = acc0 + out_b[r0];
        if (r0 + 1 < V) out[r0 + 1] = acc1 + out_b[r0 + 1];
    }
}

// K_G: fused log-softmax normalize. 64 blocks, logits held in registers
// across a global spin barrier (64 blocks are always co-resident).
__global__ __launch_bounds__(256) void k_lsesub(float* __restrict__ out) {
    __shared__ float sm[256];
    __shared__ float s_lse;
    int t = threadIdx.x;
    int gtid = blockIdx.x * 256 + t;
    float v[4];
    float m = -INFINITY;
    #pragma unroll
    for (int k = 0; k < 4; k++) {
        int i = gtid + k * (NB_LSE * 256);
        v[k] = (i < V) ? out[i] : -INFINITY;
        m = fmaxf(m, v[k]);
    }
    sm[t] = m; __syncthreads();
    #pragma unroll
    for (int s = 128; s > 0; s >>= 1) {
        if (t < s) sm[t] = fmaxf(sm[t], sm[t + s]);
        __syncthreads();
    }
    float bmax = sm[0]; __syncthreads();
    float sum = 0.f;
    #pragma unroll
    for (int k = 0; k < 4; k++)
        sum += (v[k] > -INFINITY) ? expf(v[k] - bmax) : 0.f;
    sm[t] = sum; __syncthreads();
    #pragma unroll
    for (int s = 128; s > 0; s >>= 1) {
        if (t < s) sm[t] += sm[t + s];
        __syncthreads();
    }
    if (t == 0) { g_pmax[blockIdx.x] = bmax; g_psum[blockIdx.x] = sm[0]; }
    // global barrier (epoch-based, replay-safe)
    __threadfence();
    __syncthreads();
    if (t == 0) {
        int my = g_release;
        int c = atomicAdd(&g_count, 1);
        if (c == NB_LSE - 1) {
            g_count = 0;
            __threadfence();
            atomicAdd((int*)&g_release, 1);
        } else {
            while (g_release == my) { __nanosleep(64); }
        }
        __threadfence();
        // combine partials (redundant per block, deterministic)
        float M = -INFINITY;
        for (int i = 0; i < NB_LSE; i++) M = fmaxf(M, g_pmax[i]);
        float ssum = 0.f;
        for (int i = 0; i < NB_LSE; i++) ssum += g_psum[i] * expf(g_pmax[i] - M);
        s_lse = M + logf(ssum);
    }
    __syncthreads();
    float lse = s_lse;
    #pragma unroll
    for (int k = 0; k < 4; k++) {
        int i = gtid + k * (NB_LSE * 256);
        if (i < V) out[i] = v[k] - lse;
    }
}

// ---------------------------------------------------------------------------
extern "C" void kernel_launch(void* const* d_in, const int* in_sizes, int n_in,
                              void* d_out, int out_size) {
    const int*   input_id = (const int*)  d_in[0];
    const float* hidden   = (const float*)d_in[1];
    const float* enc      = (const float*)d_in[2];
    const float* emb      = (const float*)d_in[3];
    // d_in[4], d_in[5]: attn linear — dead (softmax over singleton)
    const float* comb_w   = (const float*)d_in[6];
    const float* comb_b   = (const float*)d_in[7];
    const float* w_ih     = (const float*)d_in[8];
    const float* w_hh     = (const float*)d_in[9];
    const float* b_ih     = (const float*)d_in[10];
    const float* b_hh     = (const float*)d_in[11];
    const float* out_w    = (const float*)d_in[12];
    const float* out_b    = (const float*)d_in[13];
    float* out = (float*)d_out; // [log_probs(V) | h_new(H) | attn_weights(S)]

    k_A<<<GH_BLOCKS + CS_BLOCKS + MISC_BLOCKS, 256>>>(w_hh, b_hh, hidden, enc,
                                                      input_id, emb, out + V + H);
    k_colsum2<<<H / 256, 256>>>();
    k_comb<<<H / 16, 256>>>(comb_w, comb_b);
    k_gates_ih<<<(3 * H) / 16, 256>>>(w_ih, b_ih);
    k_gru<<<H / 256, 256>>>(hidden, out + V);
    k_out<<<(V + 15) / 16, 256>>>(out_w, out_b, out);
    k_lsesub<<<NB_LSE, 256>>>(out);
}

// round 10
// speedup vs baseline: 1.2044x; 1.0089x over previous
#include <cuda_runtime.h>
#include <math.h>

#define H 2048
#define S 2048
#define V 50257
#define RCH 16
#define NB_LSE 64

// Scratch (device globals — no allocation allowed)
__device__ float g_emb[H];
__device__ float g_part[RCH * H];
__device__ float g_x[H];
__device__ float g_gx[3 * H];
__device__ float g_gh[3 * H];
__device__ float g_hnew[H];
__device__ float g_pmax[NB_LSE];
__device__ float g_psum[NB_LSE];
__device__ int g_count;                 // zero-initialized
__device__ volatile int g_release;      // monotonic epoch

__device__ __forceinline__ float warp_reduce(float v) {
    #pragma unroll
    for (int o = 16; o > 0; o >>= 1) v += __shfl_xor_sync(0xFFFFFFFFu, v, o);
    return v;
}

// Two-row warp dot over H floats (512 float4), 4 phases of 8 in-flight LDG.128.
__device__ __forceinline__ void dot2(const float4* __restrict__ w0,
                                     const float4* __restrict__ w1,
                                     const float4* __restrict__ sx,
                                     int lane, float& acc0, float& acc1) {
    #pragma unroll
    for (int p = 0; p < 4; p++) {
        float4 a0[4], a1[4];
        #pragma unroll
        for (int b = 0; b < 4; b++) a0[b] = __ldcs(&w0[lane + 32 * (4 * p + b)]);
        #pragma unroll
        for (int b = 0; b < 4; b++) a1[b] = __ldcs(&w1[lane + 32 * (4 * p + b)]);
        #pragma unroll
        for (int b = 0; b < 4; b++) {
            float4 xv = sx[lane + 32 * (4 * p + b)];
            acc0 = fmaf(a0[b].x, xv.x, acc0); acc0 = fmaf(a0[b].y, xv.y, acc0);
            acc0 = fmaf(a0[b].z, xv.z, acc0); acc0 = fmaf(a0[b].w, xv.w, acc0);
            acc1 = fmaf(a1[b].x, xv.x, acc1); acc1 = fmaf(a1[b].y, xv.y, acc1);
            acc1 = fmaf(a1[b].z, xv.z, acc1); acc1 = fmaf(a1[b].w, xv.w, acc1);
        }
    }
}

// gh block body: 16 rows of w_hh (2/warp) against h0 staged in smem
__device__ __forceinline__ void gh_block(const float* __restrict__ w_hh,
                                         const float* __restrict__ b_hh,
                                         const float* __restrict__ h0,
                                         float4* sx, int row_base) {
    const float4* x4 = (const float4*)h0;
    sx[threadIdx.x] = x4[threadIdx.x];
    sx[threadIdx.x + 256] = x4[threadIdx.x + 256];
    __syncthreads();
    int w = threadIdx.x >> 5, lane = threadIdx.x & 31;
    int r0 = row_base + w * 2;
    const float4* w0 = (const float4*)(w_hh + (size_t)r0 * H);
    float acc0 = 0.f, acc1 = 0.f;
    dot2(w0, w0 + H / 4, sx, lane, acc0, acc1);
    acc0 = warp_reduce(acc0);
    acc1 = warp_reduce(acc1);
    if (lane == 0) {
        g_gh[r0]     = acc0 + b_hh[r0];
        g_gh[r0 + 1] = acc1 + b_hh[r0 + 1];
    }
}

// ---------------------------------------------------------------------------
// K_A: colsum partials (128) | misc (8) | gh rows 0..2047 (128 blocks)
#define CS_BLOCKS 128
#define MISC_BLOCKS 8
#define GH_A 128
__global__ __launch_bounds__(256, 3) void k_A(const float* __restrict__ w_hh,
                                              const float* __restrict__ b_hh,
                                              const float* __restrict__ h0,
                                              const float* __restrict__ enc,
                                              const int* __restrict__ input_id,
                                              const float* __restrict__ emb,
                                              float* __restrict__ out_attn) {
    __shared__ float4 sx[H / 4];
    int b = blockIdx.x;
    if (b < CS_BLOCKS) {
        int chunk = b >> 3;                      // 0..15
        int colb = b & 7;                        // 0..7
        int col = colb * 256 + threadIdx.x;
        int r0 = chunk * (S / RCH);
        float s = 0.f;
        #pragma unroll 8
        for (int r = 0; r < S / RCH; ++r)
            s += __ldcs(&enc[(size_t)(r0 + r) * H + col]);
        g_part[chunk * H + col] = s;
    } else if (b < CS_BLOCKS + MISC_BLOCKS) {
        int i = (b - CS_BLOCKS) * 256 + threadIdx.x;   // 0..2047
        g_emb[i] = emb[(size_t)(*input_id) * H + i];
        out_attn[i] = 1.0f;
    } else {
        gh_block(w_hh, b_hh, h0, sx, (b - CS_BLOCKS - MISC_BLOCKS) * 16);
    }
}

// K_C: comb matvec (128 blocks; colsum reduced in-block) | gh rows 2048..4095
#define COMB_BLOCKS 128
#define GH_C 128
__global__ __launch_bounds__(256, 3) void k_comb(const float* __restrict__ comb_w,
                                                 const float* __restrict__ comb_b,
                                                 const float* __restrict__ w_hh,
                                                 const float* __restrict__ b_hh,
                                                 const float* __restrict__ h0) {
    __shared__ float4 sbuf[2 * (H / 4)];
    int b = blockIdx.x;
    if (b < COMB_BLOCKS) {
        float4* se = sbuf;
        float4* sc = sbuf + H / 4;
        const float4* e4 = (const float4*)g_emb;
        se[threadIdx.x] = e4[threadIdx.x];
        se[threadIdx.x + 256] = e4[threadIdx.x + 256];
        // reduce colsum partials from L2 (redundant per block)
        const float4* p4 = (const float4*)g_part;
        #pragma unroll
        for (int half = 0; half < 2; half++) {
            int idx = threadIdx.x + 256 * half;
            float4 s = {0.f, 0.f, 0.f, 0.f};
            #pragma unroll
            for (int c = 0; c < RCH; ++c) {
                float4 v = p4[c * (H / 4) + idx];
                s.x += v.x; s.y += v.y; s.z += v.z; s.w += v.w;
            }
            sc[idx] = s;
        }
        __syncthreads();
        int w = threadIdx.x >> 5, lane = threadIdx.x & 31;
        int r0 = b * 16 + w * 2;                 // 0..2046
        const float4* w0 = (const float4*)(comb_w + (size_t)r0 * 2 * H);
        const float4* w1 = w0 + 2 * H / 4;
        float acc0 = 0.f, acc1 = 0.f;
        dot2(w0, w1, se, lane, acc0, acc1);                    // emb half
        dot2(w0 + H / 4, w1 + H / 4, sc, lane, acc0, acc1);    // colsum half
        acc0 = warp_reduce(acc0);
        acc1 = warp_reduce(acc1);
        if (lane == 0) {
            g_x[r0]     = fmaxf(acc0 + comb_b[r0], 0.f);
            g_x[r0 + 1] = fmaxf(acc1 + comb_b[r0 + 1], 0.f);
        }
    } else {
        gh_block(w_hh, b_hh, h0, sbuf, 2048 + (b - COMB_BLOCKS) * 16);
    }
}

// K_D: gx = w_ih @ relu_x + b_ih (384 blocks) | gh rows 4096..6143 (128 blocks)
#define GX_BLOCKS 384
#define GH_D 128
__global__ __launch_bounds__(256, 3) void k_gates_ih(const float* __restrict__ w_ih,
                                                     const float* __restrict__ b_ih,
                                                     const float* __restrict__ w_hh,
                                                     const float* __restrict__ b_hh,
                                                     const float* __restrict__ h0) {
    __shared__ float4 sx[H / 4];
    int b = blockIdx.x;
    if (b < GX_BLOCKS) {
        const float4* x4 = (const float4*)g_x;
        sx[threadIdx.x] = x4[threadIdx.x];
        sx[threadIdx.x + 256] = x4[threadIdx.x + 256];
        __syncthreads();
        int w = threadIdx.x >> 5, lane = threadIdx.x & 31;
        int r0 = b * 16 + w * 2;                 // 0..6142
        const float4* w0 = (const float4*)(w_ih + (size_t)r0 * H);
        float acc0 = 0.f, acc1 = 0.f;
        dot2(w0, w0 + H / 4, sx, lane, acc0, acc1);
        acc0 = warp_reduce(acc0);
        acc1 = warp_reduce(acc1);
        if (lane == 0) {
            g_gx[r0]     = acc0 + b_ih[r0];
            g_gx[r0 + 1] = acc1 + b_ih[r0 + 1];
        }
    } else {
        gh_block(w_hh, b_hh, h0, sx, 4096 + (b - GX_BLOCKS) * 16);
    }
}

// K_E: GRU gate combine -> h_new
__global__ void k_gru(const float* __restrict__ h0, float* __restrict__ out_h) {
    int i = blockIdx.x * 256 + threadIdx.x;
    float r = 1.f / (1.f + expf(-(g_gx[i]         + g_gh[i])));
    float z = 1.f / (1.f + expf(-(g_gx[H + i]     + g_gh[H + i])));
    float n = tanhf(g_gx[2 * H + i] + r * g_gh[2 * H + i]);
    float hn = (1.f - z) * n + z * h0[i];
    g_hnew[i] = hn;
    out_h[i]  = hn;
}

// K_F: out matvec (V rows x H cols) -> raw logits. 4 blocks/SM for more
// resident warps (multi-wave kernel: warps x MLP is what sets BW).
__global__ __launch_bounds__(256, 4) void k_out(const float* __restrict__ out_w,
                                                const float* __restrict__ out_b,
                                                float* __restrict__ out) {
    __shared__ float4 sx[H / 4];
    const float4* x4 = (const float4*)g_hnew;
    sx[threadIdx.x] = x4[threadIdx.x];
    sx[threadIdx.x + 256] = x4[threadIdx.x + 256];
    __syncthreads();
    int w = threadIdx.x >> 5, lane = threadIdx.x & 31;
    int r0 = blockIdx.x * 16 + w * 2;
    if (r0 >= V) return;
    const float4* w0 = (const float4*)(out_w + (size_t)r0 * H);
    float acc0 = 0.f, acc1 = 0.f;
    if (r0 + 1 < V) {
        dot2(w0, w0 + H / 4, sx, lane, acc0, acc1);
    } else {
        dot2(w0, w0, sx, lane, acc0, acc1);  // duplicate row; acc1 discarded
    }
    acc0 = warp_reduce(acc0);
    acc1 = warp_reduce(acc1);
    if (lane == 0) {
        out[r0] = acc0 + out_b[r0];
        if (r0 + 1 < V) out[r0 + 1] = acc1 + out_b[r0 + 1];
    }
}

// K_G: fused log-softmax normalize. 64 blocks, logits held in registers
// across a global spin barrier (64 blocks are always co-resident).
__global__ __launch_bounds__(256) void k_lsesub(float* __restrict__ out) {
    __shared__ float sm[256];
    __shared__ float s_lse;
    int t = threadIdx.x;
    int gtid = blockIdx.x * 256 + t;
    float v[4];
    float m = -INFINITY;
    #pragma unroll
    for (int k = 0; k < 4; k++) {
        int i = gtid + k * (NB_LSE * 256);
        v[k] = (i < V) ? out[i] : -INFINITY;
        m = fmaxf(m, v[k]);
    }
    sm[t] = m; __syncthreads();
    #pragma unroll
    for (int s = 128; s > 0; s >>= 1) {
        if (t < s) sm[t] = fmaxf(sm[t], sm[t + s]);
        __syncthreads();
    }
    float bmax = sm[0]; __syncthreads();
    float sum = 0.f;
    #pragma unroll
    for (int k = 0; k < 4; k++)
        sum += (v[k] > -INFINITY) ? expf(v[k] - bmax) : 0.f;
    sm[t] = sum; __syncthreads();
    #pragma unroll
    for (int s = 128; s > 0; s >>= 1) {
        if (t < s) sm[t] += sm[t + s];
        __syncthreads();
    }
    if (t == 0) { g_pmax[blockIdx.x] = bmax; g_psum[blockIdx.x] = sm[0]; }
    // global barrier (epoch-based, replay-safe)
    __threadfence();
    __syncthreads();
    if (t == 0) {
        int my = g_release;
        int c = atomicAdd(&g_count, 1);
        if (c == NB_LSE - 1) {
            g_count = 0;
            __threadfence();
            atomicAdd((int*)&g_release, 1);
        } else {
            while (g_release == my) { __nanosleep(64); }
        }
        __threadfence();
        // combine partials (redundant per block, deterministic)
        float M = -INFINITY;
        for (int i = 0; i < NB_LSE; i++) M = fmaxf(M, g_pmax[i]);
        float ssum = 0.f;
        for (int i = 0; i < NB_LSE; i++) ssum += g_psum[i] * expf(g_pmax[i] - M);
        s_lse = M + logf(ssum);
    }
    __syncthreads();
    float lse = s_lse;
    #pragma unroll
    for (int k = 0; k < 4; k++) {
        int i = gtid + k * (NB_LSE * 256);
        if (i < V) out[i] = v[k] - lse;
    }
}

// ---------------------------------------------------------------------------
extern "C" void kernel_launch(void* const* d_in, const int* in_sizes, int n_in,
                              void* d_out, int out_size) {
    const int*   input_id = (const int*)  d_in[0];
    const float* hidden   = (const float*)d_in[1];
    const float* enc      = (const float*)d_in[2];
    const float* emb      = (const float*)d_in[3];
    // d_in[4], d_in[5]: attn linear — dead (softmax over singleton)
    const float* comb_w   = (const float*)d_in[6];
    const float* comb_b   = (const float*)d_in[7];
    const float* w_ih     = (const float*)d_in[8];
    const float* w_hh     = (const float*)d_in[9];
    const float* b_ih     = (const float*)d_in[10];
    const float* b_hh     = (const float*)d_in[11];
    const float* out_w    = (const float*)d_in[12];
    const float* out_b    = (const float*)d_in[13];
    float* out = (float*)d_out; // [log_probs(V) | h_new(H) | attn_weights(S)]

    k_A<<<CS_BLOCKS + MISC_BLOCKS + GH_A, 256>>>(w_hh, b_hh, hidden, enc,
                                                 input_id, emb, out + V + H);
    k_comb<<<COMB_BLOCKS + GH_C, 256>>>(comb_w, comb_b, w_hh, b_hh, hidden);
    k_gates_ih<<<GX_BLOCKS + GH_D, 256>>>(w_ih, b_ih, w_hh, b_hh, hidden);
    k_gru<<<H / 256, 256>>>(hidden, out + V);
    k_out<<<(V + 15) / 16, 256>>>(out_w, out_b, out);
    k_lsesub<<<NB_LSE, 256>>>(out);
}